// round 9
// baseline (speedup 1.0000x reference)
#include <cuda_runtime.h>
#include <cuda_bf16.h>
#include <cstdint>
#include <math.h>

#define D_MODEL 64
#define HID     128
#define NRULES  4
#define K1      192
#define TT      8192
#define NTOK    (32*TT)
#define NBLK    (NTOK/128)       // 2048 CTAs, 128 tokens each
#define NTHR    256
#define LN_EPS  1e-5f

// pitches (uint2 units), all ≡ 4 (mod 16) -> conflict-free LDS.64
#define W1P  132      // W1 rows: 128 entries + pad
#define W2P  68       // W2 rows: 64 entries + pad
#define CP2P 36       // packed-cells rows: 32 entries + pad

// smem (bytes): packed cells 130 x CP2P u2 = 37440 | W region 101376
#define OFF_W_B 37440
#define SMEM_BYTES (37440 + 3*32*W1P*8)   // 138816

__device__ float g_rw[4];
__device__ float g_alpha;
__device__ int   g_nev;
__device__ float g_buf0[(size_t)NTOK*D_MODEL];
__device__ float g_buf1[(size_t)NTOK*D_MODEL];
// pre-packed weights, exact smem layout (incl. pitch padding)
__device__ uint2 g_w1p[NRULES*3*32*W1P];
__device__ uint2 g_w2p[NRULES*64*W2P];

__device__ __forceinline__ float gelu_exact(float x){
    return 0.5f * x * (1.0f + erff(x * 0.7071067811865475f));
}
__device__ __forceinline__ void pack_hilo(float2 v, uint32_t& hi, uint32_t& lo){
    __nv_bfloat162 hb = __float22bfloat162_rn(v);
    float2 lv;
    lv.x = v.x - __bfloat162float(hb.x);
    lv.y = v.y - __bfloat162float(hb.y);
    __nv_bfloat162 lb = __float22bfloat162_rn(lv);
    hi = *(uint32_t*)&hb;
    lo = *(uint32_t*)&lb;
}
__device__ __forceinline__ void mma_bf16(float* d,
    uint32_t a0, uint32_t a1, uint32_t a2, uint32_t a3,
    uint32_t b0, uint32_t b1)
{
    asm volatile(
        "mma.sync.aligned.m16n8k16.row.col.f32.bf16.bf16.f32 "
        "{%0,%1,%2,%3},{%4,%5,%6,%7},{%8,%9},{%0,%1,%2,%3};"
        : "+f"(d[0]), "+f"(d[1]), "+f"(d[2]), "+f"(d[3])
        : "r"(a0), "r"(a1), "r"(a2), "r"(a3), "r"(b0), "r"(b1));
}

// ---------------- one-shot weight packing ----------------
__global__ void pack_weights(const float* __restrict__ rw1,
                             const float* __restrict__ rw2)
{
    int i = blockIdx.x * blockDim.x + threadIdx.x;
    if (i < NRULES*3*32*128){
        int n  = i & 127;
        int kp = (i >> 7) & 31;
        int rs = i >> 12;            // r*3 + s
        int s  = rs % 3, r = rs / 3;
        const float* w = rw1 + ((size_t)r*K1 + s*64) * HID;
        float2 v;
        v.x = w[(size_t)(2*kp)   * HID + n];
        v.y = w[(size_t)(2*kp+1) * HID + n];
        uint32_t hi, lo;
        pack_hilo(v, hi, lo);
        g_w1p[(size_t)(rs*32 + kp)*W1P + n] = make_uint2(hi, lo);
    } else {
        int q = i - NRULES*3*32*128;     // 0..16383
        if (q >= NRULES*64*64) return;
        int n  = q & 63;
        int kp = (q >> 6) & 63;
        int r  = q >> 12;
        const float* w = rw2 + (size_t)r * HID * D_MODEL;
        float2 v;
        v.x = w[(size_t)(2*kp)   * D_MODEL + n];
        v.y = w[(size_t)(2*kp+1) * D_MODEL + n];
        uint32_t hi, lo;
        pack_hilo(v, hi, lo);
        g_w2p[(size_t)(r*64 + kp)*W2P + n] = make_uint2(hi, lo);
    }
}

// ---------------- control kernel ----------------
__global__ void control_kernel(
    const float* __restrict__ c,
    const float* __restrict__ sw1, const float* __restrict__ sb1,
    const float* __restrict__ sw2, const float* __restrict__ sb2,
    const float* __restrict__ tw1, const float* __restrict__ tb1,
    const float* __restrict__ tw2, const float* __restrict__ tb2,
    const float* __restrict__ qw1, const float* __restrict__ qb1,
    const float* __restrict__ qw2, const float* __restrict__ qb2)
{
    __shared__ float cs[128], h1[64], h2[32], h3[32];
    int t = threadIdx.x;
    if (t < 128) cs[t] = c[t];
    __syncthreads();
    if (t < 64){
        float a = sb1[t];
        for (int k = 0; k < 128; k++) a += cs[k] * sw1[k*64 + t];
        h1[t] = gelu_exact(a);
    } else if (t < 96){
        int i = t - 64; float a = tb1[i];
        for (int k = 0; k < 128; k++) a += cs[k] * tw1[k*32 + i];
        h2[i] = gelu_exact(a);
    } else {
        int i = t - 96; float a = qb1[i];
        for (int k = 0; k < 128; k++) a += cs[k] * qw1[k*32 + i];
        h3[i] = gelu_exact(a);
    }
    __syncthreads();
    if (t == 0){
        float l[4], mx = -1e30f;
        for (int r = 0; r < 4; r++){
            float a = sb2[r];
            for (int i = 0; i < 64; i++) a += h1[i] * sw2[i*4 + r];
            l[r] = a; mx = fmaxf(mx, a);
        }
        float s = 0.f;
        for (int r = 0; r < 4; r++){ l[r] = expf(l[r]-mx); s += l[r]; }
        for (int r = 0; r < 4; r++) g_rw[r] = l[r]/s;
    }
    if (t == 1){
        float l[7], mx = -1e30f;
        for (int q = 0; q < 7; q++){
            float a = tb2[q];
            for (int i = 0; i < 32; i++) a += h2[i] * tw2[i*7 + q];
            l[q] = a; mx = fmaxf(mx, a);
        }
        float s = 0.f;
        for (int q = 0; q < 7; q++){ l[q] = expf(l[q]-mx); s += l[q]; }
        float nf = 0.f;
        for (int q = 0; q < 7; q++) nf += (l[q]/s) * (float)(q+2);
        int n = (int)(nf + 0.5f);
        g_nev = n < 2 ? 2 : (n > 8 ? 8 : n);
    }
    if (t == 2){
        float v = qb2[0];
        for (int i = 0; i < 32; i++) v += h3[i] * qw2[i];
        g_alpha = 0.1f + 0.8f / (1.0f + expf(-v));
    }
}

// ---------------- evolve step ----------------
__global__ void __launch_bounds__(NTHR, 1)
step_kernel(const float* __restrict__ cells_in,
            const float* __restrict__ rb1, const float* __restrict__ rb2,
            int j)
{
    if (j >= g_nev) return;

    extern __shared__ char smc[];
    uint2* cp = (uint2*)smc;               // packed cells: 130 x CP2P
    uint2* ws = (uint2*)(smc + OFF_W_B);   // W1 (3 segs) / W2 staging

    const float* src = (j == 0) ? cells_in : ((j & 1) ? g_buf0 : g_buf1);
    float*       dst = (j & 1) ? g_buf1 : g_buf0;

    const int tid  = threadIdx.x;
    const int w    = tid >> 5;
    const int lane = tid & 31;
    const int g    = lane >> 2;
    const int tig  = lane & 3;
    const int m0   = w * 16;

    const int brow = blockIdx.x >> 6;
    const int t0   = (blockIdx.x & 63) << 7;
    const float* rowbase = src + (size_t)brow * TT * D_MODEL;

    // build packed hi/lo cells halo tile ONCE (rows t0-1 .. t0+128)
    for (int i = tid; i < 130*32; i += NTHR){
        int row = i >> 5, kp = i & 31;
        int t = (t0 - 1 + row) & (TT - 1);
        float2 v = *(const float2*)(rowbase + (size_t)t * D_MODEL + 2*kp);
        uint32_t hi, lo;
        pack_hilo(v, hi, lo);
        cp[row*CP2P + kp] = make_uint2(hi, lo);
    }

    float outa[32];
    #pragma unroll
    for (int i = 0; i < 32; i++) outa[i] = 0.0f;

    const int soffs[3] = {1, 0, 2};

    for (int r = 0; r < NRULES; r++){
        __syncthreads();    // cp ready (r=0) / prior GEMM2 done with ws

        // stage W1 all 3 segs: linear copy of pre-packed data (101376 B)
        {
            const uint4* srcw = (const uint4*)(g_w1p + (size_t)r*3*32*W1P);
            uint4* dstw = (uint4*)ws;
            #pragma unroll 5
            for (int i = tid; i < 3*32*W1P/2; i += NTHR) dstw[i] = srcw[i];
        }
        __syncthreads();

        // ========== GEMM1: C1[128x128] = X3[128x192] @ W1 (3-term bf16) ====
        float acc[16][4];
        #pragma unroll
        for (int a = 0; a < 16; a++){
            acc[a][0] = 0.f; acc[a][1] = 0.f; acc[a][2] = 0.f; acc[a][3] = 0.f;
        }
        #pragma unroll
        for (int seg = 0; seg < 3; seg++){
            const uint2* wseg = ws + seg*32*W1P;
            const uint2* apr  = cp + (size_t)(m0 + soffs[seg] + g) * CP2P;
            const uint2* bpr  = apr + 8*CP2P;
            #pragma unroll
            for (int kt = 0; kt < 4; kt++){
                const int kp = kt*8 + tig;
                uint2 A0 = apr[kp], A1 = bpr[kp];
                uint2 A2 = apr[kp+4], A3 = bpr[kp+4];
                const uint2* b0r = wseg + (size_t)kp*W1P;
                const uint2* b1r = b0r + 4*W1P;
                #pragma unroll
                for (int nt = 0; nt < 16; nt++){
                    int nc = nt*8 + g;
                    uint2 p0 = b0r[nc], p1 = b1r[nc];
                    mma_bf16(acc[nt], A0.x,A1.x,A2.x,A3.x, p0.x, p1.x);
                    mma_bf16(acc[nt], A0.y,A1.y,A2.y,A3.y, p0.x, p1.x);
                    mma_bf16(acc[nt], A0.x,A1.x,A2.x,A3.x, p0.y, p1.y);
                }
            }
        }

        // ===== epilogue1 in registers: h = gelu(C1+b1) -> GEMM2 A fragments
        uint32_t fh[8][4], fl[8][4];
        #pragma unroll
        for (int kt = 0; kt < 8; kt++){
            #pragma unroll
            for (int half = 0; half < 2; half++){
                int nt = 2*kt + half;
                int c  = nt*8 + 2*tig;
                const float2 b = __ldg((const float2*)(rb1 + r*HID + c));
                float2 va, vb;
                va.x = gelu_exact(acc[nt][0] + b.x);
                va.y = gelu_exact(acc[nt][1] + b.y);
                vb.x = gelu_exact(acc[nt][2] + b.x);
                vb.y = gelu_exact(acc[nt][3] + b.y);
                pack_hilo(va, fh[kt][half*2],   fl[kt][half*2]);
                pack_hilo(vb, fh[kt][half*2+1], fl[kt][half*2+1]);
            }
        }

        __syncthreads();    // all warps done reading W1 region

        // stage W2: linear copy (34816 B)
        {
            const uint4* srcw = (const uint4*)(g_w2p + (size_t)r*64*W2P);
            uint4* dstw = (uint4*)ws;
            #pragma unroll 5
            for (int i = tid; i < 64*W2P/2; i += NTHR) dstw[i] = srcw[i];
        }
        __syncthreads();

        // ========== GEMM2: C2[128x64] = h @ W2 (A from registers) ==========
        float acc2[8][4];
        #pragma unroll
        for (int a = 0; a < 8; a++){
            acc2[a][0] = 0.f; acc2[a][1] = 0.f; acc2[a][2] = 0.f; acc2[a][3] = 0.f;
        }
        #pragma unroll
        for (int kt = 0; kt < 8; kt++){
            const uint2* b0r = ws + (size_t)(kt*8 + tig)*W2P;
            const uint2* b1r = b0r + 4*W2P;
            #pragma unroll
            for (int nt = 0; nt < 8; nt++){
                int nc = nt*8 + g;
                uint2 p0 = b0r[nc], p1 = b1r[nc];
                mma_bf16(acc2[nt], fh[kt][0],fh[kt][1],fh[kt][2],fh[kt][3], p0.x, p1.x);
                mma_bf16(acc2[nt], fl[kt][0],fl[kt][1],fl[kt][2],fl[kt][3], p0.x, p1.x);
                mma_bf16(acc2[nt], fh[kt][0],fh[kt][1],fh[kt][2],fh[kt][3], p0.y, p1.y);
            }
        }

        // epilogue2: outa += rw[r] * tanh(C2 + b2)
        {
            const float rr = g_rw[r];
            #pragma unroll
            for (int nt = 0; nt < 8; nt++){
                int c = nt*8 + 2*tig;
                const float2 b = __ldg((const float2*)(rb2 + r*D_MODEL + c));
                outa[nt*4+0] += rr * tanhf(acc2[nt][0] + b.x);
                outa[nt*4+1] += rr * tanhf(acc2[nt][1] + b.y);
                outa[nt*4+2] += rr * tanhf(acc2[nt][2] + b.x);
                outa[nt*4+3] += rr * tanhf(acc2[nt][3] + b.y);
            }
        }
    }

    // residual mix + store (fp32 cells reloaded from gmem, L2-hot)
    {
        const float al = g_alpha, om = 1.0f - al;
        const float* sra = src + ((size_t)brow*TT + t0 + m0 + g) * D_MODEL;
        const float* srb = src + ((size_t)brow*TT + t0 + m0 + g + 8) * D_MODEL;
        float* da = dst + ((size_t)brow*TT + t0 + m0 + g) * D_MODEL;
        float* db = dst + ((size_t)brow*TT + t0 + m0 + g + 8) * D_MODEL;
        #pragma unroll
        for (int nt = 0; nt < 8; nt++){
            int c = nt*8 + 2*tig;
            float2 cva = __ldg((const float2*)(sra + c));
            float2 cvb = __ldg((const float2*)(srb + c));
            float2 oa, ob;
            oa.x = al*cva.x + om*outa[nt*4+0];
            oa.y = al*cva.y + om*outa[nt*4+1];
            ob.x = al*cvb.x + om*outa[nt*4+2];
            ob.y = al*cvb.y + om*outa[nt*4+3];
            *(float2*)(da + c) = oa;
            *(float2*)(db + c) = ob;
        }
    }
}

// ---------------- final LayerNorm ----------------
__global__ void __launch_bounds__(256)
ln_kernel(const float* __restrict__ g, const float* __restrict__ b,
          float* __restrict__ out)
{
    const float* src = ((g_nev - 1) & 1) ? g_buf1 : g_buf0;
    int tok  = blockIdx.x * 8 + (threadIdx.x >> 5);
    int lane = threadIdx.x & 31;
    float2 v = ((const float2*)(src + (size_t)tok * D_MODEL))[lane];
    float s = v.x + v.y;
    #pragma unroll
    for (int o = 16; o; o >>= 1) s += __shfl_xor_sync(0xffffffffu, s, o);
    float mu = s * (1.0f/64.0f);
    float dx = v.x - mu, dy = v.y - mu;
    float ss = dx*dx + dy*dy;
    #pragma unroll
    for (int o = 16; o; o >>= 1) ss += __shfl_xor_sync(0xffffffffu, ss, o);
    float rstd = rsqrtf(ss * (1.0f/64.0f) + LN_EPS);
    float2 gg = ((const float2*)g)[lane];
    float2 bb = ((const float2*)b)[lane];
    float2 ov;
    ov.x = dx * rstd * gg.x + bb.x;
    ov.y = dy * rstd * gg.y + bb.y;
    ((float2*)(out + (size_t)tok * D_MODEL))[lane] = ov;
}

// ---------------- launch ----------------
extern "C" void kernel_launch(void* const* d_in, const int* in_sizes, int n_in,
                              void* d_out, int out_size)
{
    const float* cells = (const float*)d_in[0];
    cudaFuncSetAttribute(step_kernel,
                         cudaFuncAttributeMaxDynamicSharedMemorySize, SMEM_BYTES);

    control_kernel<<<1, 128>>>((const float*)d_in[1],
        (const float*)d_in[6],  (const float*)d_in[7],
        (const float*)d_in[8],  (const float*)d_in[9],
        (const float*)d_in[10], (const float*)d_in[11],
        (const float*)d_in[12], (const float*)d_in[13],
        (const float*)d_in[14], (const float*)d_in[15],
        (const float*)d_in[16], (const float*)d_in[17]);

    pack_weights<<<(NRULES*3*32*128 + NRULES*64*64 + 255)/256, 256>>>(
        (const float*)d_in[2], (const float*)d_in[4]);

    for (int j = 0; j < 8; j++)
        step_kernel<<<NBLK, NTHR, SMEM_BYTES>>>(cells,
            (const float*)d_in[3], (const float*)d_in[5], j);

    ln_kernel<<<NTOK/8, 256>>>((const float*)d_in[18], (const float*)d_in[19],
                               (float*)d_out);
}

// round 10
// speedup vs baseline: 1.0765x; 1.0765x over previous
#include <cuda_runtime.h>
#include <cuda_bf16.h>
#include <cstdint>
#include <math.h>

#define D_MODEL 64
#define HID     128
#define NRULES  4
#define K1      192
#define TT      8192
#define NTOK    (32*TT)
#define NBLK    (NTOK/128)       // 2048 CTAs, 128 tokens each
#define NTHR    512
#define LN_EPS  1e-5f

// pitches (uint2 units), ≡ 4 (mod 16) -> conflict-free LDS.64
#define W1P  132
#define W2P  68
#define CP2P 36

// smem: packed cells 130*36 u2 = 37440 B | ws: W1 3 segs = 101376 B
//       (W2 overlays ws[0..34816), xchg buffer overlays ws[34816..67584))
#define OFF_W_B 37440
#define OFF_X_B (OFF_W_B + 34816)
#define SMEM_BYTES (OFF_W_B + 3*32*W1P*8)   // 138816

__device__ float g_rw[4];
__device__ float g_alpha;
__device__ int   g_nev;
__device__ float g_buf0[(size_t)NTOK*D_MODEL];
__device__ float g_buf1[(size_t)NTOK*D_MODEL];
__device__ uint2 g_w1p[NRULES*3*32*W1P];
__device__ uint2 g_w2p[NRULES*64*W2P];

__device__ __forceinline__ float gelu_exact(float x){
    return 0.5f * x * (1.0f + erff(x * 0.7071067811865475f));
}
__device__ __forceinline__ void pack_hilo(float2 v, uint32_t& hi, uint32_t& lo){
    __nv_bfloat162 hb = __float22bfloat162_rn(v);
    float2 lv;
    lv.x = v.x - __bfloat162float(hb.x);
    lv.y = v.y - __bfloat162float(hb.y);
    __nv_bfloat162 lb = __float22bfloat162_rn(lv);
    hi = *(uint32_t*)&hb;
    lo = *(uint32_t*)&lb;
}
__device__ __forceinline__ void mma_bf16(float* d,
    uint32_t a0, uint32_t a1, uint32_t a2, uint32_t a3,
    uint32_t b0, uint32_t b1)
{
    asm volatile(
        "mma.sync.aligned.m16n8k16.row.col.f32.bf16.bf16.f32 "
        "{%0,%1,%2,%3},{%4,%5,%6,%7},{%8,%9},{%0,%1,%2,%3};"
        : "+f"(d[0]), "+f"(d[1]), "+f"(d[2]), "+f"(d[3])
        : "r"(a0), "r"(a1), "r"(a2), "r"(a3), "r"(b0), "r"(b1));
}

// ---------------- one-shot weight packing ----------------
__global__ void pack_weights(const float* __restrict__ rw1,
                             const float* __restrict__ rw2)
{
    int i = blockIdx.x * blockDim.x + threadIdx.x;
    if (i < NRULES*3*32*128){
        int n  = i & 127;
        int kp = (i >> 7) & 31;
        int rs = i >> 12;
        int s  = rs % 3, r = rs / 3;
        const float* w = rw1 + ((size_t)r*K1 + s*64) * HID;
        float2 v;
        v.x = w[(size_t)(2*kp)   * HID + n];
        v.y = w[(size_t)(2*kp+1) * HID + n];
        uint32_t hi, lo;
        pack_hilo(v, hi, lo);
        g_w1p[(size_t)(rs*32 + kp)*W1P + n] = make_uint2(hi, lo);
    } else {
        int q = i - NRULES*3*32*128;
        if (q >= NRULES*64*64) return;
        int n  = q & 63;
        int kp = (q >> 6) & 63;
        int r  = q >> 12;
        const float* w = rw2 + (size_t)r * HID * D_MODEL;
        float2 v;
        v.x = w[(size_t)(2*kp)   * D_MODEL + n];
        v.y = w[(size_t)(2*kp+1) * D_MODEL + n];
        uint32_t hi, lo;
        pack_hilo(v, hi, lo);
        g_w2p[(size_t)(r*64 + kp)*W2P + n] = make_uint2(hi, lo);
    }
}

// ---------------- control kernel ----------------
__global__ void control_kernel(
    const float* __restrict__ c,
    const float* __restrict__ sw1, const float* __restrict__ sb1,
    const float* __restrict__ sw2, const float* __restrict__ sb2,
    const float* __restrict__ tw1, const float* __restrict__ tb1,
    const float* __restrict__ tw2, const float* __restrict__ tb2,
    const float* __restrict__ qw1, const float* __restrict__ qb1,
    const float* __restrict__ qw2, const float* __restrict__ qb2)
{
    __shared__ float cs[128], h1[64], h2[32], h3[32];
    int t = threadIdx.x;
    if (t < 128) cs[t] = c[t];
    __syncthreads();
    if (t < 64){
        float a = sb1[t];
        for (int k = 0; k < 128; k++) a += cs[k] * sw1[k*64 + t];
        h1[t] = gelu_exact(a);
    } else if (t < 96){
        int i = t - 64; float a = tb1[i];
        for (int k = 0; k < 128; k++) a += cs[k] * tw1[k*32 + i];
        h2[i] = gelu_exact(a);
    } else {
        int i = t - 96; float a = qb1[i];
        for (int k = 0; k < 128; k++) a += cs[k] * qw1[k*32 + i];
        h3[i] = gelu_exact(a);
    }
    __syncthreads();
    if (t == 0){
        float l[4], mx = -1e30f;
        for (int r = 0; r < 4; r++){
            float a = sb2[r];
            for (int i = 0; i < 64; i++) a += h1[i] * sw2[i*4 + r];
            l[r] = a; mx = fmaxf(mx, a);
        }
        float s = 0.f;
        for (int r = 0; r < 4; r++){ l[r] = expf(l[r]-mx); s += l[r]; }
        for (int r = 0; r < 4; r++) g_rw[r] = l[r]/s;
    }
    if (t == 1){
        float l[7], mx = -1e30f;
        for (int q = 0; q < 7; q++){
            float a = tb2[q];
            for (int i = 0; i < 32; i++) a += h2[i] * tw2[i*7 + q];
            l[q] = a; mx = fmaxf(mx, a);
        }
        float s = 0.f;
        for (int q = 0; q < 7; q++){ l[q] = expf(l[q]-mx); s += l[q]; }
        float nf = 0.f;
        for (int q = 0; q < 7; q++) nf += (l[q]/s) * (float)(q+2);
        int n = (int)(nf + 0.5f);
        g_nev = n < 2 ? 2 : (n > 8 ? 8 : n);
    }
    if (t == 2){
        float v = qb2[0];
        for (int i = 0; i < 32; i++) v += h3[i] * qw2[i];
        g_alpha = 0.1f + 0.8f / (1.0f + expf(-v));
    }
}

// ---------------- evolve step (16 warps, n-split warp pairs) ----------------
__global__ void __launch_bounds__(NTHR, 1)
step_kernel(const float* __restrict__ cells_in,
            const float* __restrict__ rb1, const float* __restrict__ rb2,
            int j)
{
    if (j >= g_nev) return;

    extern __shared__ char smc[];
    uint2*  cp = (uint2*)smc;
    uint2*  ws = (uint2*)(smc + OFF_W_B);
    float4* xb = (float4*)(smc + OFF_X_B);

    const float* src = (j == 0) ? cells_in : ((j & 1) ? g_buf0 : g_buf1);
    float*       dst = (j & 1) ? g_buf1 : g_buf0;

    const int tid  = threadIdx.x;
    const int w    = tid >> 5;
    const int lane = tid & 31;
    const int g    = lane >> 2;
    const int tig  = lane & 3;
    const int half = w >> 3;          // 0: cols 0-63 / kt 0-3; 1: cols 64-127 / kt 4-7
    const int wp   = w & 7;           // pair id
    const int m0   = wp * 16;

    const int brow = blockIdx.x >> 6;
    const int t0   = (blockIdx.x & 63) << 7;
    const float* rowbase = src + (size_t)brow * TT * D_MODEL;

    // build packed hi/lo cells halo tile once (rows t0-1 .. t0+128)
    for (int i = tid; i < 130*32; i += NTHR){
        int row = i >> 5, kp = i & 31;
        int t = (t0 - 1 + row) & (TT - 1);
        float2 v = *(const float2*)(rowbase + (size_t)t * D_MODEL + 2*kp);
        uint32_t hi, lo;
        pack_hilo(v, hi, lo);
        cp[row*CP2P + kp] = make_uint2(hi, lo);
    }

    float outa[16];
    #pragma unroll
    for (int i = 0; i < 16; i++) outa[i] = 0.0f;

    const int soffs[3] = {1, 0, 2};

    for (int r = 0; r < NRULES; r++){
        __syncthreads();   // cp ready (r=0) / xchg reads done (r>0)

        // stage W1 all 3 segs (linear copy of pre-packed uint2)
        {
            const uint4* srcw = (const uint4*)(g_w1p + (size_t)r*3*32*W1P);
            uint4* dstw = (uint4*)ws;
            #pragma unroll
            for (int i = tid; i < 3*32*W1P/2; i += NTHR) dstw[i] = srcw[i];
        }
        __syncthreads();

        // ===== GEMM1: this warp computes C1 rows [m0,m0+16) x cols [half*64 .. +64)
        float acc[8][4];
        #pragma unroll
        for (int a = 0; a < 8; a++){
            acc[a][0] = 0.f; acc[a][1] = 0.f; acc[a][2] = 0.f; acc[a][3] = 0.f;
        }
        #pragma unroll
        for (int seg = 0; seg < 3; seg++){
            const uint2* wseg = ws + seg*32*W1P;
            const uint2* apr  = cp + (size_t)(m0 + soffs[seg] + g) * CP2P;
            const uint2* bpr  = apr + 8*CP2P;
            #pragma unroll
            for (int kt = 0; kt < 4; kt++){
                const int kp = kt*8 + tig;
                uint2 A0 = apr[kp],   A1 = bpr[kp];
                uint2 A2 = apr[kp+4], A3 = bpr[kp+4];
                const uint2* b0r = wseg + (size_t)kp*W1P;
                const uint2* b1r = b0r + 4*W1P;
                #pragma unroll
                for (int ntl = 0; ntl < 8; ntl++){
                    int nc = (half*8 + ntl)*8 + g;
                    uint2 p0 = b0r[nc], p1 = b1r[nc];
                    mma_bf16(acc[ntl], A0.x,A1.x,A2.x,A3.x, p0.x, p1.x);
                    mma_bf16(acc[ntl], A0.y,A1.y,A2.y,A3.y, p0.x, p1.x);
                    mma_bf16(acc[ntl], A0.x,A1.x,A2.x,A3.x, p0.y, p1.y);
                }
            }
        }

        // ===== epilogue1 in regs: h = gelu(C1+b1) -> GEMM2 A frags kt = half*4+ktl
        uint32_t fh[4][4], fl[4][4];
        #pragma unroll
        for (int ktl = 0; ktl < 4; ktl++){
            #pragma unroll
            for (int sub = 0; sub < 2; sub++){
                int ntl = 2*ktl + sub;
                int c   = (half*8 + ntl)*8 + 2*tig;
                const float2 b = __ldg((const float2*)(rb1 + r*HID + c));
                float2 va, vb;
                va.x = gelu_exact(acc[ntl][0] + b.x);
                va.y = gelu_exact(acc[ntl][1] + b.y);
                vb.x = gelu_exact(acc[ntl][2] + b.x);
                vb.y = gelu_exact(acc[ntl][3] + b.y);
                pack_hilo(va, fh[ktl][sub*2],   fl[ktl][sub*2]);
                pack_hilo(vb, fh[ktl][sub*2+1], fl[ktl][sub*2+1]);
            }
        }
        __syncthreads();   // all warps done reading W1 region

        // stage W2 (overlays ws[0..34816))
        {
            const uint4* srcw = (const uint4*)(g_w2p + (size_t)r*64*W2P);
            uint4* dstw = (uint4*)ws;
            #pragma unroll
            for (int i = tid; i < 64*W2P/2; i += NTHR) dstw[i] = srcw[i];
        }
        __syncthreads();

        // ===== GEMM2 partial: k-chunks kt = half*4 .. half*4+3, all 8 n-tiles
        float acc2[8][4];
        #pragma unroll
        for (int a = 0; a < 8; a++){
            acc2[a][0] = 0.f; acc2[a][1] = 0.f; acc2[a][2] = 0.f; acc2[a][3] = 0.f;
        }
        #pragma unroll
        for (int ktl = 0; ktl < 4; ktl++){
            const int ktg = half*4 + ktl;
            const uint2* b0r = ws + (size_t)(ktg*8 + tig)*W2P;
            const uint2* b1r = b0r + 4*W2P;
            #pragma unroll
            for (int nt = 0; nt < 8; nt++){
                int nc = nt*8 + g;
                uint2 p0 = b0r[nc], p1 = b1r[nc];
                mma_bf16(acc2[nt], fh[ktl][0],fh[ktl][1],fh[ktl][2],fh[ktl][3], p0.x, p1.x);
                mma_bf16(acc2[nt], fl[ktl][0],fl[ktl][1],fl[ktl][2],fl[ktl][3], p0.x, p1.x);
                mma_bf16(acc2[nt], fh[ktl][0],fh[ktl][1],fh[ktl][2],fh[ktl][3], p0.y, p1.y);
            }
        }

        // exchange: store the 4 n-tiles the PARTNER finalizes
        {
            const int sbase = (wp*2 + half)*4;          // own slot
            const int snt   = half ? 0 : 4;             // store nt 4..7 (wa) / 0..3 (wb)
            #pragma unroll
            for (int q = 0; q < 4; q++)
                xb[(sbase + q)*32 + lane] = make_float4(
                    acc2[snt+q][0], acc2[snt+q][1], acc2[snt+q][2], acc2[snt+q][3]);
        }
        __syncthreads();

        // finalize: own kept half + partner partial -> tanh -> outa
        {
            const int pbase = (wp*2 + (1 - half))*4;    // partner slot
            const float rr = g_rw[r];
            #pragma unroll
            for (int q = 0; q < 4; q++){
                int ntf = half*4 + q;
                float4 pp = xb[(pbase + q)*32 + lane];
                int c = ntf*8 + 2*tig;
                const float2 b = __ldg((const float2*)(rb2 + r*D_MODEL + c));
                outa[q*4+0] += rr * tanhf(acc2[ntf][0] + pp.x + b.x);
                outa[q*4+1] += rr * tanhf(acc2[ntf][1] + pp.y + b.y);
                outa[q*4+2] += rr * tanhf(acc2[ntf][2] + pp.z + b.x);
                outa[q*4+3] += rr * tanhf(acc2[ntf][3] + pp.w + b.y);
            }
        }
    }

    // residual mix + store: rows m0+g / m0+g+8, cols [half*32 .. +32)
    {
        const float al = g_alpha, om = 1.0f - al;
        const float* sra = src + ((size_t)brow*TT + t0 + m0 + g) * D_MODEL;
        const float* srb = src + ((size_t)brow*TT + t0 + m0 + g + 8) * D_MODEL;
        float* da = dst + ((size_t)brow*TT + t0 + m0 + g) * D_MODEL;
        float* db = dst + ((size_t)brow*TT + t0 + m0 + g + 8) * D_MODEL;
        #pragma unroll
        for (int q = 0; q < 4; q++){
            int c = (half*4 + q)*8 + 2*tig;
            float2 cva = __ldg((const float2*)(sra + c));
            float2 cvb = __ldg((const float2*)(srb + c));
            float2 oa, ob;
            oa.x = al*cva.x + om*outa[q*4+0];
            oa.y = al*cva.y + om*outa[q*4+1];
            ob.x = al*cvb.x + om*outa[q*4+2];
            ob.y = al*cvb.y + om*outa[q*4+3];
            *(float2*)(da + c) = oa;
            *(float2*)(db + c) = ob;
        }
    }
}

// ---------------- final LayerNorm ----------------
__global__ void __launch_bounds__(256)
ln_kernel(const float* __restrict__ g, const float* __restrict__ b,
          float* __restrict__ out)
{
    const float* src = ((g_nev - 1) & 1) ? g_buf1 : g_buf0;
    int tok  = blockIdx.x * 8 + (threadIdx.x >> 5);
    int lane = threadIdx.x & 31;
    float2 v = ((const float2*)(src + (size_t)tok * D_MODEL))[lane];
    float s = v.x + v.y;
    #pragma unroll
    for (int o = 16; o; o >>= 1) s += __shfl_xor_sync(0xffffffffu, s, o);
    float mu = s * (1.0f/64.0f);
    float dx = v.x - mu, dy = v.y - mu;
    float ss = dx*dx + dy*dy;
    #pragma unroll
    for (int o = 16; o; o >>= 1) ss += __shfl_xor_sync(0xffffffffu, ss, o);
    float rstd = rsqrtf(ss * (1.0f/64.0f) + LN_EPS);
    float2 gg = ((const float2*)g)[lane];
    float2 bb = ((const float2*)b)[lane];
    float2 ov;
    ov.x = dx * rstd * gg.x + bb.x;
    ov.y = dy * rstd * gg.y + bb.y;
    ((float2*)(out + (size_t)tok * D_MODEL))[lane] = ov;
}

// ---------------- launch ----------------
extern "C" void kernel_launch(void* const* d_in, const int* in_sizes, int n_in,
                              void* d_out, int out_size)
{
    const float* cells = (const float*)d_in[0];
    cudaFuncSetAttribute(step_kernel,
                         cudaFuncAttributeMaxDynamicSharedMemorySize, SMEM_BYTES);

    control_kernel<<<1, 128>>>((const float*)d_in[1],
        (const float*)d_in[6],  (const float*)d_in[7],
        (const float*)d_in[8],  (const float*)d_in[9],
        (const float*)d_in[10], (const float*)d_in[11],
        (const float*)d_in[12], (const float*)d_in[13],
        (const float*)d_in[14], (const float*)d_in[15],
        (const float*)d_in[16], (const float*)d_in[17]);

    pack_weights<<<(NRULES*3*32*128 + NRULES*64*64 + 255)/256, 256>>>(
        (const float*)d_in[2], (const float*)d_in[4]);

    for (int j = 0; j < 8; j++)
        step_kernel<<<NBLK, NTHR, SMEM_BYTES>>>(cells,
            (const float*)d_in[3], (const float*)d_in[5], j);

    ln_kernel<<<NTOK/8, 256>>>((const float*)d_in[18], (const float*)d_in[19],
                               (float*)d_out);
}

// round 11
// speedup vs baseline: 1.1100x; 1.0311x over previous
#include <cuda_runtime.h>
#include <cuda_bf16.h>
#include <cstdint>
#include <math.h>

#define D_MODEL 64
#define HID     128
#define NRULES  4
#define K1      192
#define TT      8192
#define NTOK    (32*TT)
#define NBLK    (NTOK/128)
#define NTHR    512
#define LN_EPS  1e-5f

// pitches (uint2 units), ≡ 4 (mod 16) -> conflict-free LDS.64
#define W1P  132
#define W2P  68
#define CP2P 36

#define SEG_BYTES (32*W1P*8)      // 33792
#define SEG_U4    (SEG_BYTES/16)  // 2112
#define W2_BYTES  (64*W2P*8)      // 34816
#define W2_U4     (W2_BYTES/16)   // 2176

// smem layout (bytes)
#define OFF_W0B  37440
#define OFF_W1B  (OFF_W0B + SEG_BYTES)          // 71232
#define OFF_W2B  (OFF_W1B + SEG_BYTES)          // 105024
#define OFF_XCHB (OFF_W2B + W2_BYTES)           // 139840
#define SMEM_BYTES (OFF_XCHB + 32768)           // 172608

__device__ float g_rw[4];
__device__ float g_alpha;
__device__ int   g_nev;
__device__ float g_buf0[(size_t)NTOK*D_MODEL];
__device__ float g_buf1[(size_t)NTOK*D_MODEL];
__device__ __align__(16) uint2 g_w1p[NRULES*3*32*W1P];
__device__ __align__(16) uint2 g_w2p[NRULES*64*W2P];

__device__ __forceinline__ float gelu_exact(float x){
    return 0.5f * x * (1.0f + erff(x * 0.7071067811865475f));
}
__device__ __forceinline__ float tanh_fast(float x){
    float e = __expf(2.0f*x);
    return 1.0f - __fdividef(2.0f, e + 1.0f);
}
__device__ __forceinline__ void pack_hilo(float2 v, uint32_t& hi, uint32_t& lo){
    __nv_bfloat162 hb = __float22bfloat162_rn(v);
    float2 lv;
    lv.x = v.x - __bfloat162float(hb.x);
    lv.y = v.y - __bfloat162float(hb.y);
    __nv_bfloat162 lb = __float22bfloat162_rn(lv);
    hi = *(uint32_t*)&hb;
    lo = *(uint32_t*)&lb;
}
__device__ __forceinline__ void mma_bf16(float* d,
    uint32_t a0, uint32_t a1, uint32_t a2, uint32_t a3,
    uint32_t b0, uint32_t b1)
{
    asm volatile(
        "mma.sync.aligned.m16n8k16.row.col.f32.bf16.bf16.f32 "
        "{%0,%1,%2,%3},{%4,%5,%6,%7},{%8,%9},{%0,%1,%2,%3};"
        : "+f"(d[0]), "+f"(d[1]), "+f"(d[2]), "+f"(d[3])
        : "r"(a0), "r"(a1), "r"(a2), "r"(a3), "r"(b0), "r"(b1));
}

// async 16B copy helper
__device__ __forceinline__ void cp_copy16(void* dst, const void* src, int n16, int tid){
    uint32_t sbase = (uint32_t)__cvta_generic_to_shared(dst);
    const uint4* s = (const uint4*)src;
    for (int i = tid; i < n16; i += NTHR)
        asm volatile("cp.async.cg.shared.global [%0], [%1], 16;"
                     :: "r"(sbase + i*16), "l"(s + i));
}
#define CP_COMMIT() asm volatile("cp.async.commit_group;" ::: "memory")
#define CP_WAIT0()  asm volatile("cp.async.wait_group 0;" ::: "memory")

// ---------------- one-shot weight packing ----------------
__global__ void pack_weights(const float* __restrict__ rw1,
                             const float* __restrict__ rw2)
{
    int i = blockIdx.x * blockDim.x + threadIdx.x;
    if (i < NRULES*3*32*128){
        int n  = i & 127;
        int kp = (i >> 7) & 31;
        int rs = i >> 12;
        int s  = rs % 3, r = rs / 3;
        const float* w = rw1 + ((size_t)r*K1 + s*64) * HID;
        float2 v;
        v.x = w[(size_t)(2*kp)   * HID + n];
        v.y = w[(size_t)(2*kp+1) * HID + n];
        uint32_t hi, lo;
        pack_hilo(v, hi, lo);
        g_w1p[(size_t)(rs*32 + kp)*W1P + n] = make_uint2(hi, lo);
    } else {
        int q = i - NRULES*3*32*128;
        if (q >= NRULES*64*64) return;
        int n  = q & 63;
        int kp = (q >> 6) & 63;
        int r  = q >> 12;
        const float* w = rw2 + (size_t)r * HID * D_MODEL;
        float2 v;
        v.x = w[(size_t)(2*kp)   * D_MODEL + n];
        v.y = w[(size_t)(2*kp+1) * D_MODEL + n];
        uint32_t hi, lo;
        pack_hilo(v, hi, lo);
        g_w2p[(size_t)(r*64 + kp)*W2P + n] = make_uint2(hi, lo);
    }
}

// ---------------- control kernel ----------------
__global__ void control_kernel(
    const float* __restrict__ c,
    const float* __restrict__ sw1, const float* __restrict__ sb1,
    const float* __restrict__ sw2, const float* __restrict__ sb2,
    const float* __restrict__ tw1, const float* __restrict__ tb1,
    const float* __restrict__ tw2, const float* __restrict__ tb2,
    const float* __restrict__ qw1, const float* __restrict__ qb1,
    const float* __restrict__ qw2, const float* __restrict__ qb2)
{
    __shared__ float cs[128], h1[64], h2[32], h3[32];
    int t = threadIdx.x;
    if (t < 128) cs[t] = c[t];
    __syncthreads();
    if (t < 64){
        float a = sb1[t];
        for (int k = 0; k < 128; k++) a += cs[k] * sw1[k*64 + t];
        h1[t] = gelu_exact(a);
    } else if (t < 96){
        int i = t - 64; float a = tb1[i];
        for (int k = 0; k < 128; k++) a += cs[k] * tw1[k*32 + i];
        h2[i] = gelu_exact(a);
    } else {
        int i = t - 96; float a = qb1[i];
        for (int k = 0; k < 128; k++) a += cs[k] * qw1[k*32 + i];
        h3[i] = gelu_exact(a);
    }
    __syncthreads();
    if (t == 0){
        float l[4], mx = -1e30f;
        for (int r = 0; r < 4; r++){
            float a = sb2[r];
            for (int i = 0; i < 64; i++) a += h1[i] * sw2[i*4 + r];
            l[r] = a; mx = fmaxf(mx, a);
        }
        float s = 0.f;
        for (int r = 0; r < 4; r++){ l[r] = expf(l[r]-mx); s += l[r]; }
        for (int r = 0; r < 4; r++) g_rw[r] = l[r]/s;
    }
    if (t == 1){
        float l[7], mx = -1e30f;
        for (int q = 0; q < 7; q++){
            float a = tb2[q];
            for (int i = 0; i < 32; i++) a += h2[i] * tw2[i*7 + q];
            l[q] = a; mx = fmaxf(mx, a);
        }
        float s = 0.f;
        for (int q = 0; q < 7; q++){ l[q] = expf(l[q]-mx); s += l[q]; }
        float nf = 0.f;
        for (int q = 0; q < 7; q++) nf += (l[q]/s) * (float)(q+2);
        int n = (int)(nf + 0.5f);
        g_nev = n < 2 ? 2 : (n > 8 ? 8 : n);
    }
    if (t == 2){
        float v = qb2[0];
        for (int i = 0; i < 32; i++) v += h3[i] * qw2[i];
        g_alpha = 0.1f + 0.8f / (1.0f + expf(-v));
    }
}

// one GEMM1 segment: 4 k-tiles x 8 n-tiles x 3 terms
__device__ __forceinline__ void gemm1_seg(float acc[8][4], const uint2* wseg,
    const uint2* apr, const uint2* bpr, int half, int g, int tig)
{
    #pragma unroll
    for (int kt = 0; kt < 4; kt++){
        const int kp = kt*8 + tig;
        uint2 A0 = apr[kp],   A1 = bpr[kp];
        uint2 A2 = apr[kp+4], A3 = bpr[kp+4];
        const uint2* b0r = wseg + (size_t)kp*W1P;
        const uint2* b1r = b0r + 4*W1P;
        #pragma unroll
        for (int ntl = 0; ntl < 8; ntl++){
            int nc = (half*8 + ntl)*8 + g;
            uint2 p0 = b0r[nc], p1 = b1r[nc];
            mma_bf16(acc[ntl], A0.x,A1.x,A2.x,A3.x, p0.x, p1.x);
            mma_bf16(acc[ntl], A0.y,A1.y,A2.y,A3.y, p0.x, p1.x);
            mma_bf16(acc[ntl], A0.x,A1.x,A2.x,A3.x, p0.y, p1.y);
        }
    }
}

// ---------------- evolve step (16 warps, cp.async pipelined) ----------------
__global__ void __launch_bounds__(NTHR, 1)
step_kernel(const float* __restrict__ cells_in,
            const float* __restrict__ rb1, const float* __restrict__ rb2,
            int j)
{
    if (j >= g_nev) return;

    extern __shared__ char smc[];
    uint2*  cp  = (uint2*)smc;
    uint2*  wb0 = (uint2*)(smc + OFF_W0B);
    uint2*  wb1 = (uint2*)(smc + OFF_W1B);
    uint2*  w2s = (uint2*)(smc + OFF_W2B);
    float4* xb  = (float4*)(smc + OFF_XCHB);
    uint2*  wb[2] = {wb0, wb1};

    const float* src = (j == 0) ? cells_in : ((j & 1) ? g_buf0 : g_buf1);
    float*       dst = (j & 1) ? g_buf1 : g_buf0;

    const int tid  = threadIdx.x;
    const int w    = tid >> 5;
    const int lane = tid & 31;
    const int g    = lane >> 2;
    const int tig  = lane & 3;
    const int half = w >> 3;
    const int wp   = w & 7;
    const int m0   = wp * 16;

    const int brow = blockIdx.x >> 6;
    const int t0   = (blockIdx.x & 63) << 7;
    const float* rowbase = src + (size_t)brow * TT * D_MODEL;

    // prefetch rule0 seg0 while building the cells tile
    cp_copy16(wb0, g_w1p, SEG_U4, tid);
    CP_COMMIT();

    for (int i = tid; i < 130*32; i += NTHR){
        int row = i >> 5, kp = i & 31;
        int t = (t0 - 1 + row) & (TT - 1);
        float2 v = *(const float2*)(rowbase + (size_t)t * D_MODEL + 2*kp);
        uint32_t hi, lo;
        pack_hilo(v, hi, lo);
        cp[row*CP2P + kp] = make_uint2(hi, lo);
    }
    CP_WAIT0();
    __syncthreads();

    float outa[16];
    #pragma unroll
    for (int i = 0; i < 16; i++) outa[i] = 0.0f;

    for (int r = 0; r < NRULES; r++){
        const int b = r & 1;
        const uint2* apr0 = cp + (size_t)(m0 + 1 + g) * CP2P;   // seg0: cells[t]
        const uint2* apr1 = cp + (size_t)(m0 + 0 + g) * CP2P;   // seg1: cells[t-1]
        const uint2* apr2 = cp + (size_t)(m0 + 2 + g) * CP2P;   // seg2: cells[t+1]

        float acc[8][4];
        #pragma unroll
        for (int a = 0; a < 8; a++){
            acc[a][0]=0.f; acc[a][1]=0.f; acc[a][2]=0.f; acc[a][3]=0.f;
        }

        // [A] prefetch seg1 + W2(r); compute seg0
        cp_copy16(wb[b^1], g_w1p + (size_t)(r*3+1)*32*W1P, SEG_U4, tid);
        cp_copy16(w2s,     g_w2p + (size_t)r*64*W2P,       W2_U4,  tid);
        CP_COMMIT();
        gemm1_seg(acc, wb[b], apr0, apr0 + 8*CP2P, half, g, tig);
        CP_WAIT0();
        __syncthreads();

        // [B] prefetch seg2; compute seg1
        cp_copy16(wb[b], g_w1p + (size_t)(r*3+2)*32*W1P, SEG_U4, tid);
        CP_COMMIT();
        gemm1_seg(acc, wb[b^1], apr1, apr1 + 8*CP2P, half, g, tig);
        CP_WAIT0();
        __syncthreads();

        // [C] prefetch next rule seg0; compute seg2
        if (r < NRULES-1)
            cp_copy16(wb[b^1], g_w1p + (size_t)((r+1)*3)*32*W1P, SEG_U4, tid);
        CP_COMMIT();
        gemm1_seg(acc, wb[b], apr2, apr2 + 8*CP2P, half, g, tig);

        // epi1 in registers: h = gelu(C1+b1) -> GEMM2 A fragments
        uint32_t fh[4][4], fl[4][4];
        #pragma unroll
        for (int ktl = 0; ktl < 4; ktl++){
            #pragma unroll
            for (int sub = 0; sub < 2; sub++){
                int ntl = 2*ktl + sub;
                int c   = (half*8 + ntl)*8 + 2*tig;
                const float2 bb = __ldg((const float2*)(rb1 + r*HID + c));
                float2 va, vb;
                va.x = gelu_exact(acc[ntl][0] + bb.x);
                va.y = gelu_exact(acc[ntl][1] + bb.y);
                vb.x = gelu_exact(acc[ntl][2] + bb.x);
                vb.y = gelu_exact(acc[ntl][3] + bb.y);
                pack_hilo(va, fh[ktl][sub*2],   fl[ktl][sub*2]);
                pack_hilo(vb, fh[ktl][sub*2+1], fl[ktl][sub*2+1]);
            }
        }

        // GEMM2 pass1: PARTNER's n-tiles (store early), k-chunks half*4..+3
        float acc2[4][4];
        {
            #pragma unroll
            for (int a = 0; a < 4; a++){
                acc2[a][0]=0.f; acc2[a][1]=0.f; acc2[a][2]=0.f; acc2[a][3]=0.f;
            }
            const int ntb = half ? 0 : 4;
            #pragma unroll
            for (int ktl = 0; ktl < 4; ktl++){
                const uint2* b0r = w2s + (size_t)((half*4+ktl)*8 + tig)*W2P;
                const uint2* b1r = b0r + 4*W2P;
                #pragma unroll
                for (int q = 0; q < 4; q++){
                    int nc = (ntb+q)*8 + g;
                    uint2 p0 = b0r[nc], p1 = b1r[nc];
                    mma_bf16(acc2[q], fh[ktl][0],fh[ktl][1],fh[ktl][2],fh[ktl][3], p0.x, p1.x);
                    mma_bf16(acc2[q], fl[ktl][0],fl[ktl][1],fl[ktl][2],fl[ktl][3], p0.x, p1.x);
                    mma_bf16(acc2[q], fh[ktl][0],fh[ktl][1],fh[ktl][2],fh[ktl][3], p0.y, p1.y);
                }
            }
            const int sbase = (wp*2 + half)*4;
            #pragma unroll
            for (int q = 0; q < 4; q++)
                xb[(sbase + q)*32 + lane] =
                    make_float4(acc2[q][0], acc2[q][1], acc2[q][2], acc2[q][3]);
        }

        // GEMM2 pass2: OWN n-tiles
        {
            #pragma unroll
            for (int a = 0; a < 4; a++){
                acc2[a][0]=0.f; acc2[a][1]=0.f; acc2[a][2]=0.f; acc2[a][3]=0.f;
            }
            const int ntb = half*4;
            #pragma unroll
            for (int ktl = 0; ktl < 4; ktl++){
                const uint2* b0r = w2s + (size_t)((half*4+ktl)*8 + tig)*W2P;
                const uint2* b1r = b0r + 4*W2P;
                #pragma unroll
                for (int q = 0; q < 4; q++){
                    int nc = (ntb+q)*8 + g;
                    uint2 p0 = b0r[nc], p1 = b1r[nc];
                    mma_bf16(acc2[q], fh[ktl][0],fh[ktl][1],fh[ktl][2],fh[ktl][3], p0.x, p1.x);
                    mma_bf16(acc2[q], fl[ktl][0],fl[ktl][1],fl[ktl][2],fl[ktl][3], p0.x, p1.x);
                    mma_bf16(acc2[q], fh[ktl][0],fh[ktl][1],fh[ktl][2],fh[ktl][3], p0.y, p1.y);
                }
            }
        }
        CP_WAIT0();
        __syncthreads();   // xchg visible + next seg0 staged

        // finalize: own partial + partner partial -> tanh -> outa
        {
            const int pbase = (wp*2 + (1 - half))*4;
            const float rr = g_rw[r];
            #pragma unroll
            for (int q = 0; q < 4; q++){
                float4 pp = xb[(pbase + q)*32 + lane];
                int c = (half*4 + q)*8 + 2*tig;
                const float2 bb = __ldg((const float2*)(rb2 + r*D_MODEL + c));
                outa[q*4+0] += rr * tanh_fast(acc2[q][0] + pp.x + bb.x);
                outa[q*4+1] += rr * tanh_fast(acc2[q][1] + pp.y + bb.y);
                outa[q*4+2] += rr * tanh_fast(acc2[q][2] + pp.z + bb.x);
                outa[q*4+3] += rr * tanh_fast(acc2[q][3] + pp.w + bb.y);
            }
        }
    }

    // residual mix + store
    {
        const float al = g_alpha, om = 1.0f - al;
        const float* sra = src + ((size_t)brow*TT + t0 + m0 + g) * D_MODEL;
        const float* srb = src + ((size_t)brow*TT + t0 + m0 + g + 8) * D_MODEL;
        float* da = dst + ((size_t)brow*TT + t0 + m0 + g) * D_MODEL;
        float* db = dst + ((size_t)brow*TT + t0 + m0 + g + 8) * D_MODEL;
        #pragma unroll
        for (int q = 0; q < 4; q++){
            int c = (half*4 + q)*8 + 2*tig;
            float2 cva = __ldg((const float2*)(sra + c));
            float2 cvb = __ldg((const float2*)(srb + c));
            float2 oa, ob;
            oa.x = al*cva.x + om*outa[q*4+0];
            oa.y = al*cva.y + om*outa[q*4+1];
            ob.x = al*cvb.x + om*outa[q*4+2];
            ob.y = al*cvb.y + om*outa[q*4+3];
            *(float2*)(da + c) = oa;
            *(float2*)(db + c) = ob;
        }
    }
}

// ---------------- final LayerNorm ----------------
__global__ void __launch_bounds__(256)
ln_kernel(const float* __restrict__ g, const float* __restrict__ b,
          float* __restrict__ out)
{
    const float* src = ((g_nev - 1) & 1) ? g_buf1 : g_buf0;
    int tok  = blockIdx.x * 8 + (threadIdx.x >> 5);
    int lane = threadIdx.x & 31;
    float2 v = ((const float2*)(src + (size_t)tok * D_MODEL))[lane];
    float s = v.x + v.y;
    #pragma unroll
    for (int o = 16; o; o >>= 1) s += __shfl_xor_sync(0xffffffffu, s, o);
    float mu = s * (1.0f/64.0f);
    float dx = v.x - mu, dy = v.y - mu;
    float ss = dx*dx + dy*dy;
    #pragma unroll
    for (int o = 16; o; o >>= 1) ss += __shfl_xor_sync(0xffffffffu, ss, o);
    float rstd = rsqrtf(ss * (1.0f/64.0f) + LN_EPS);
    float2 gg = ((const float2*)g)[lane];
    float2 bb = ((const float2*)b)[lane];
    float2 ov;
    ov.x = dx * rstd * gg.x + bb.x;
    ov.y = dy * rstd * gg.y + bb.y;
    ((float2*)(out + (size_t)tok * D_MODEL))[lane] = ov;
}

// ---------------- launch ----------------
extern "C" void kernel_launch(void* const* d_in, const int* in_sizes, int n_in,
                              void* d_out, int out_size)
{
    const float* cells = (const float*)d_in[0];
    cudaFuncSetAttribute(step_kernel,
                         cudaFuncAttributeMaxDynamicSharedMemorySize, SMEM_BYTES);

    control_kernel<<<1, 128>>>((const float*)d_in[1],
        (const float*)d_in[6],  (const float*)d_in[7],
        (const float*)d_in[8],  (const float*)d_in[9],
        (const float*)d_in[10], (const float*)d_in[11],
        (const float*)d_in[12], (const float*)d_in[13],
        (const float*)d_in[14], (const float*)d_in[15],
        (const float*)d_in[16], (const float*)d_in[17]);

    pack_weights<<<(NRULES*3*32*128 + NRULES*64*64 + 255)/256, 256>>>(
        (const float*)d_in[2], (const float*)d_in[4]);

    for (int j = 0; j < 8; j++)
        step_kernel<<<NBLK, NTHR, SMEM_BYTES>>>(cells,
            (const float*)d_in[3], (const float*)d_in[5], j);

    ln_kernel<<<NTOK/8, 256>>>((const float*)d_in[18], (const float*)d_in[19],
                               (float*)d_out);
}

// round 12
// speedup vs baseline: 1.1380x; 1.0252x over previous
#include <cuda_runtime.h>
#include <cuda_bf16.h>
#include <cstdint>
#include <math.h>

#define D_MODEL 64
#define HID     128
#define NRULES  4
#define K1      192
#define TT      8192
#define NTOK    (32*TT)
#define NBLK    (NTOK/128)
#define NTHR    512
#define LN_EPS  1e-5f

#define CP2P 36                    // cells pitch (uint2), conflict-free LDS.64
#define W1P4 130                   // W1 pitch (uint4), ≡2 mod 8 -> conflict-free LDS.128
#define W2P4 66                    // W2 pitch (uint4), ≡2 mod 8

#define SEG_BYTES (16*W1P4*16)     // 33280
#define SEG_U4    (SEG_BYTES/16)   // 2080
#define W2_BYTES  (32*W2P4*16)     // 33792
#define W2_U4     (W2_BYTES/16)    // 2112

// smem layout (bytes)
#define OFF_W0B  37440
#define OFF_W1B  (OFF_W0B + SEG_BYTES)     // 70720
#define OFF_W2B  (OFF_W1B + SEG_BYTES)     // 104000
#define OFF_XCHB (OFF_W2B + W2_BYTES)      // 137792
#define SMEM_BYTES (OFF_XCHB + 32768)      // 170560

__device__ float g_rw[4];
__device__ float g_alpha;
__device__ int   g_nev;
__device__ float g_buf0[(size_t)NTOK*D_MODEL];
__device__ float g_buf1[(size_t)NTOK*D_MODEL];
// pre-packed weights in uint4 B-fragment layout
__device__ __align__(16) uint4 g_w1p4[NRULES*3*SEG_U4];
__device__ __align__(16) uint4 g_w2p4[NRULES*W2_U4];

__device__ __forceinline__ float gelu_exact(float x){
    return 0.5f * x * (1.0f + erff(x * 0.7071067811865475f));
}
// A&S 7.1.26 erf (abs err <= 1.5e-7) -> exact-GELU within ~1e-6
__device__ __forceinline__ float gelu_fast(float x){
    float z  = 0.70710678118f * x;
    float az = fabsf(z);
    float t  = __fdividef(1.0f, fmaf(0.3275911f, az, 1.0f));
    float p  = t*fmaf(t, fmaf(t, fmaf(t, fmaf(t, 1.061405429f, -1.453152027f),
                1.421413741f), -0.284496736f), 0.254829592f);
    float e  = __expf(-z*z);
    float er = copysignf(fmaf(-p, e, 1.0f), z);
    return 0.5f * x * (1.0f + er);
}
__device__ __forceinline__ float tanh_fast(float x){
    float e = __expf(2.0f*x);
    return 1.0f - __fdividef(2.0f, e + 1.0f);
}
__device__ __forceinline__ void pack_hilo(float2 v, uint32_t& hi, uint32_t& lo){
    __nv_bfloat162 hb = __float22bfloat162_rn(v);
    float2 lv;
    lv.x = v.x - __bfloat162float(hb.x);
    lv.y = v.y - __bfloat162float(hb.y);
    __nv_bfloat162 lb = __float22bfloat162_rn(lv);
    hi = *(uint32_t*)&hb;
    lo = *(uint32_t*)&lb;
}
__device__ __forceinline__ void mma_bf16(float* d,
    uint32_t a0, uint32_t a1, uint32_t a2, uint32_t a3,
    uint32_t b0, uint32_t b1)
{
    asm volatile(
        "mma.sync.aligned.m16n8k16.row.col.f32.bf16.bf16.f32 "
        "{%0,%1,%2,%3},{%4,%5,%6,%7},{%8,%9},{%0,%1,%2,%3};"
        : "+f"(d[0]), "+f"(d[1]), "+f"(d[2]), "+f"(d[3])
        : "r"(a0), "r"(a1), "r"(a2), "r"(a3), "r"(b0), "r"(b1));
}

__device__ __forceinline__ void cp_copy16(void* dst, const void* src, int n16, int tid){
    uint32_t sbase = (uint32_t)__cvta_generic_to_shared(dst);
    const uint4* s = (const uint4*)src;
    for (int i = tid; i < n16; i += NTHR)
        asm volatile("cp.async.cg.shared.global [%0], [%1], 16;"
                     :: "r"(sbase + i*16), "l"(s + i));
}
#define CP_COMMIT() asm volatile("cp.async.commit_group;" ::: "memory")
#define CP_WAIT0()  asm volatile("cp.async.wait_group 0;" ::: "memory")

// ---------------- one-shot weight packing (uint4 fragment layout) ----------
// entry[(kt*4+tig)*pitch + n] = {hi(k-pair kp), lo(kp), hi(kp+4), lo(kp+4)},
// kp = kt*8 + tig, k-pair kp covers source rows (2kp, 2kp+1).
__global__ void pack_weights(const float* __restrict__ rw1,
                             const float* __restrict__ rw2)
{
    int i = blockIdx.x * blockDim.x + threadIdx.x;
    if (i < NRULES*3*16*128){
        int n    = i & 127;
        int rowq = (i >> 7) & 15;
        int rs   = i >> 11;
        int kt = rowq >> 2, tig = rowq & 3;
        int kp = kt*8 + tig;
        const float* w = rw1 + ((size_t)(rs/3)*K1 + (rs%3)*64) * HID;
        float2 v0, v1;
        v0.x = w[(size_t)(2*kp)   * HID + n];
        v0.y = w[(size_t)(2*kp+1) * HID + n];
        v1.x = w[(size_t)(2*kp+8) * HID + n];
        v1.y = w[(size_t)(2*kp+9) * HID + n];
        uint32_t h0,l0,h1,l1;
        pack_hilo(v0, h0, l0);
        pack_hilo(v1, h1, l1);
        g_w1p4[(size_t)rs*SEG_U4 + rowq*W1P4 + n] = make_uint4(h0,l0,h1,l1);
    } else {
        int q = i - NRULES*3*16*128;
        if (q >= NRULES*32*64) return;
        int n    = q & 63;
        int rowq = (q >> 6) & 31;
        int r    = q >> 11;
        int ktg = rowq >> 2, tig = rowq & 3;
        int kp = ktg*8 + tig;
        const float* w = rw2 + (size_t)r * HID * D_MODEL;
        float2 v0, v1;
        v0.x = w[(size_t)(2*kp)   * D_MODEL + n];
        v0.y = w[(size_t)(2*kp+1) * D_MODEL + n];
        v1.x = w[(size_t)(2*kp+8) * D_MODEL + n];
        v1.y = w[(size_t)(2*kp+9) * D_MODEL + n];
        uint32_t h0,l0,h1,l1;
        pack_hilo(v0, h0, l0);
        pack_hilo(v1, h1, l1);
        g_w2p4[(size_t)r*W2_U4 + rowq*W2P4 + n] = make_uint4(h0,l0,h1,l1);
    }
}

// ---------------- control kernel ----------------
__global__ void control_kernel(
    const float* __restrict__ c,
    const float* __restrict__ sw1, const float* __restrict__ sb1,
    const float* __restrict__ sw2, const float* __restrict__ sb2,
    const float* __restrict__ tw1, const float* __restrict__ tb1,
    const float* __restrict__ tw2, const float* __restrict__ tb2,
    const float* __restrict__ qw1, const float* __restrict__ qb1,
    const float* __restrict__ qw2, const float* __restrict__ qb2)
{
    __shared__ float cs[128], h1[64], h2[32], h3[32];
    int t = threadIdx.x;
    if (t < 128) cs[t] = c[t];
    __syncthreads();
    if (t < 64){
        float a = sb1[t];
        for (int k = 0; k < 128; k++) a += cs[k] * sw1[k*64 + t];
        h1[t] = gelu_exact(a);
    } else if (t < 96){
        int i = t - 64; float a = tb1[i];
        for (int k = 0; k < 128; k++) a += cs[k] * tw1[k*32 + i];
        h2[i] = gelu_exact(a);
    } else {
        int i = t - 96; float a = qb1[i];
        for (int k = 0; k < 128; k++) a += cs[k] * qw1[k*32 + i];
        h3[i] = gelu_exact(a);
    }
    __syncthreads();
    if (t == 0){
        float l[4], mx = -1e30f;
        for (int r = 0; r < 4; r++){
            float a = sb2[r];
            for (int i = 0; i < 64; i++) a += h1[i] * sw2[i*4 + r];
            l[r] = a; mx = fmaxf(mx, a);
        }
        float s = 0.f;
        for (int r = 0; r < 4; r++){ l[r] = expf(l[r]-mx); s += l[r]; }
        for (int r = 0; r < 4; r++) g_rw[r] = l[r]/s;
    }
    if (t == 1){
        float l[7], mx = -1e30f;
        for (int q = 0; q < 7; q++){
            float a = tb2[q];
            for (int i = 0; i < 32; i++) a += h2[i] * tw2[i*7 + q];
            l[q] = a; mx = fmaxf(mx, a);
        }
        float s = 0.f;
        for (int q = 0; q < 7; q++){ l[q] = expf(l[q]-mx); s += l[q]; }
        float nf = 0.f;
        for (int q = 0; q < 7; q++) nf += (l[q]/s) * (float)(q+2);
        int n = (int)(nf + 0.5f);
        g_nev = n < 2 ? 2 : (n > 8 ? 8 : n);
    }
    if (t == 2){
        float v = qb2[0];
        for (int i = 0; i < 32; i++) v += h3[i] * qw2[i];
        g_alpha = 0.1f + 0.8f / (1.0f + expf(-v));
    }
}

// one GEMM1 segment: 4 k-tiles x 8 n-tiles x 3 terms (B via LDS.128)
__device__ __forceinline__ void gemm1_seg(float acc[8][4], const uint4* wseg,
    const uint2* apr, const uint2* bpr, int half, int g, int tig)
{
    #pragma unroll
    for (int kt = 0; kt < 4; kt++){
        const int kp = kt*8 + tig;
        uint2 A0 = apr[kp],   A1 = bpr[kp];
        uint2 A2 = apr[kp+4], A3 = bpr[kp+4];
        const uint4* br = wseg + (size_t)(kt*4 + tig)*W1P4;
        #pragma unroll
        for (int ntl = 0; ntl < 8; ntl++){
            uint4 qv = br[(half*8 + ntl)*8 + g];
            mma_bf16(acc[ntl], A0.x,A1.x,A2.x,A3.x, qv.x, qv.z);
            mma_bf16(acc[ntl], A0.y,A1.y,A2.y,A3.y, qv.x, qv.z);
            mma_bf16(acc[ntl], A0.x,A1.x,A2.x,A3.x, qv.y, qv.w);
        }
    }
}

// ---------------- evolve step ----------------
__global__ void __launch_bounds__(NTHR, 1)
step_kernel(const float* __restrict__ cells_in,
            const float* __restrict__ rb1, const float* __restrict__ rb2,
            int j)
{
    if (j >= g_nev) return;

    extern __shared__ char smc[];
    uint2*  cp  = (uint2*)smc;
    uint4*  wb0 = (uint4*)(smc + OFF_W0B);
    uint4*  wb1 = (uint4*)(smc + OFF_W1B);
    uint4*  w2s = (uint4*)(smc + OFF_W2B);
    float4* xb  = (float4*)(smc + OFF_XCHB);
    uint4*  wb[2] = {wb0, wb1};

    const float* src = (j == 0) ? cells_in : ((j & 1) ? g_buf0 : g_buf1);
    float*       dst = (j & 1) ? g_buf1 : g_buf0;

    const int tid  = threadIdx.x;
    const int w    = tid >> 5;
    const int lane = tid & 31;
    const int g    = lane >> 2;
    const int tig  = lane & 3;
    const int half = w >> 3;
    const int wp   = w & 7;
    const int m0   = wp * 16;

    const int brow = blockIdx.x >> 6;
    const int t0   = (blockIdx.x & 63) << 7;
    const float* rowbase = src + (size_t)brow * TT * D_MODEL;

    // prefetch rule0 seg0 while building the cells tile
    cp_copy16(wb0, g_w1p4, SEG_U4, tid);
    CP_COMMIT();

    for (int i = tid; i < 130*32; i += NTHR){
        int row = i >> 5, kp = i & 31;
        int t = (t0 - 1 + row) & (TT - 1);
        float2 v = *(const float2*)(rowbase + (size_t)t * D_MODEL + 2*kp);
        uint32_t hi, lo;
        pack_hilo(v, hi, lo);
        cp[row*CP2P + kp] = make_uint2(hi, lo);
    }
    CP_WAIT0();
    __syncthreads();

    float outa[16];
    #pragma unroll
    for (int i = 0; i < 16; i++) outa[i] = 0.0f;

    for (int r = 0; r < NRULES; r++){
        const int b = r & 1;
        const uint2* apr0 = cp + (size_t)(m0 + 1 + g) * CP2P;   // cells[t]
        const uint2* apr1 = cp + (size_t)(m0 + 0 + g) * CP2P;   // cells[t-1]
        const uint2* apr2 = cp + (size_t)(m0 + 2 + g) * CP2P;   // cells[t+1]

        float acc[8][4];
        #pragma unroll
        for (int a = 0; a < 8; a++){
            acc[a][0]=0.f; acc[a][1]=0.f; acc[a][2]=0.f; acc[a][3]=0.f;
        }

        // [A] prefetch seg1 + W2(r); compute seg0
        cp_copy16(wb[b^1], g_w1p4 + (size_t)(r*3+1)*SEG_U4, SEG_U4, tid);
        cp_copy16(w2s,     g_w2p4 + (size_t)r*W2_U4,        W2_U4,  tid);
        CP_COMMIT();
        gemm1_seg(acc, wb[b], apr0, apr0 + 8*CP2P, half, g, tig);
        CP_WAIT0();
        __syncthreads();

        // [B] prefetch seg2; compute seg1
        cp_copy16(wb[b], g_w1p4 + (size_t)(r*3+2)*SEG_U4, SEG_U4, tid);
        CP_COMMIT();
        gemm1_seg(acc, wb[b^1], apr1, apr1 + 8*CP2P, half, g, tig);
        CP_WAIT0();
        __syncthreads();

        // [C] prefetch next rule seg0; compute seg2
        if (r < NRULES-1)
            cp_copy16(wb[b^1], g_w1p4 + (size_t)((r+1)*3)*SEG_U4, SEG_U4, tid);
        CP_COMMIT();
        gemm1_seg(acc, wb[b], apr2, apr2 + 8*CP2P, half, g, tig);

        // epi1 in registers: h = gelu(C1+b1) -> GEMM2 A fragments
        uint32_t fh[4][4], fl[4][4];
        #pragma unroll
        for (int ktl = 0; ktl < 4; ktl++){
            #pragma unroll
            for (int sub = 0; sub < 2; sub++){
                int ntl = 2*ktl + sub;
                int c   = (half*8 + ntl)*8 + 2*tig;
                const float2 bb = __ldg((const float2*)(rb1 + r*HID + c));
                float2 va, vb;
                va.x = gelu_fast(acc[ntl][0] + bb.x);
                va.y = gelu_fast(acc[ntl][1] + bb.y);
                vb.x = gelu_fast(acc[ntl][2] + bb.x);
                vb.y = gelu_fast(acc[ntl][3] + bb.y);
                pack_hilo(va, fh[ktl][sub*2],   fl[ktl][sub*2]);
                pack_hilo(vb, fh[ktl][sub*2+1], fl[ktl][sub*2+1]);
            }
        }

        // GEMM2 pass1: PARTNER's n-tiles, k-chunks half*4..+3
        float acc2[4][4];
        {
            #pragma unroll
            for (int a = 0; a < 4; a++){
                acc2[a][0]=0.f; acc2[a][1]=0.f; acc2[a][2]=0.f; acc2[a][3]=0.f;
            }
            const int ntb = half ? 0 : 4;
            #pragma unroll
            for (int ktl = 0; ktl < 4; ktl++){
                const uint4* br = w2s + (size_t)((half*4+ktl)*4 + tig)*W2P4;
                #pragma unroll
                for (int q = 0; q < 4; q++){
                    uint4 qv = br[(ntb+q)*8 + g];
                    mma_bf16(acc2[q], fh[ktl][0],fh[ktl][1],fh[ktl][2],fh[ktl][3], qv.x, qv.z);
                    mma_bf16(acc2[q], fl[ktl][0],fl[ktl][1],fl[ktl][2],fl[ktl][3], qv.x, qv.z);
                    mma_bf16(acc2[q], fh[ktl][0],fh[ktl][1],fh[ktl][2],fh[ktl][3], qv.y, qv.w);
                }
            }
            const int sbase = (wp*2 + half)*4;
            #pragma unroll
            for (int q = 0; q < 4; q++)
                xb[(sbase + q)*32 + lane] =
                    make_float4(acc2[q][0], acc2[q][1], acc2[q][2], acc2[q][3]);
        }

        // GEMM2 pass2: OWN n-tiles
        {
            #pragma unroll
            for (int a = 0; a < 4; a++){
                acc2[a][0]=0.f; acc2[a][1]=0.f; acc2[a][2]=0.f; acc2[a][3]=0.f;
            }
            const int ntb = half*4;
            #pragma unroll
            for (int ktl = 0; ktl < 4; ktl++){
                const uint4* br = w2s + (size_t)((half*4+ktl)*4 + tig)*W2P4;
                #pragma unroll
                for (int q = 0; q < 4; q++){
                    uint4 qv = br[(ntb+q)*8 + g];
                    mma_bf16(acc2[q], fh[ktl][0],fh[ktl][1],fh[ktl][2],fh[ktl][3], qv.x, qv.z);
                    mma_bf16(acc2[q], fl[ktl][0],fl[ktl][1],fl[ktl][2],fl[ktl][3], qv.x, qv.z);
                    mma_bf16(acc2[q], fh[ktl][0],fh[ktl][1],fh[ktl][2],fh[ktl][3], qv.y, qv.w);
                }
            }
        }
        CP_WAIT0();
        __syncthreads();   // xchg visible + next seg0 staged

        // finalize: own partial + partner partial -> tanh -> outa
        {
            const int pbase = (wp*2 + (1 - half))*4;
            const float rr = g_rw[r];
            #pragma unroll
            for (int q = 0; q < 4; q++){
                float4 pp = xb[(pbase + q)*32 + lane];
                int c = (half*4 + q)*8 + 2*tig;
                const float2 bb = __ldg((const float2*)(rb2 + r*D_MODEL + c));
                outa[q*4+0] += rr * tanh_fast(acc2[q][0] + pp.x + bb.x);
                outa[q*4+1] += rr * tanh_fast(acc2[q][1] + pp.y + bb.y);
                outa[q*4+2] += rr * tanh_fast(acc2[q][2] + pp.z + bb.x);
                outa[q*4+3] += rr * tanh_fast(acc2[q][3] + pp.w + bb.y);
            }
        }
    }

    // residual mix + store
    {
        const float al = g_alpha, om = 1.0f - al;
        const float* sra = src + ((size_t)brow*TT + t0 + m0 + g) * D_MODEL;
        const float* srb = src + ((size_t)brow*TT + t0 + m0 + g + 8) * D_MODEL;
        float* da = dst + ((size_t)brow*TT + t0 + m0 + g) * D_MODEL;
        float* db = dst + ((size_t)brow*TT + t0 + m0 + g + 8) * D_MODEL;
        #pragma unroll
        for (int q = 0; q < 4; q++){
            int c = (half*4 + q)*8 + 2*tig;
            float2 cva = __ldg((const float2*)(sra + c));
            float2 cvb = __ldg((const float2*)(srb + c));
            float2 oa, ob;
            oa.x = al*cva.x + om*outa[q*4+0];
            oa.y = al*cva.y + om*outa[q*4+1];
            ob.x = al*cvb.x + om*outa[q*4+2];
            ob.y = al*cvb.y + om*outa[q*4+3];
            *(float2*)(da + c) = oa;
            *(float2*)(db + c) = ob;
        }
    }
}

// ---------------- final LayerNorm ----------------
__global__ void __launch_bounds__(256)
ln_kernel(const float* __restrict__ g, const float* __restrict__ b,
          float* __restrict__ out)
{
    const float* src = ((g_nev - 1) & 1) ? g_buf1 : g_buf0;
    int tok  = blockIdx.x * 8 + (threadIdx.x >> 5);
    int lane = threadIdx.x & 31;
    float2 v = ((const float2*)(src + (size_t)tok * D_MODEL))[lane];
    float s = v.x + v.y;
    #pragma unroll
    for (int o = 16; o; o >>= 1) s += __shfl_xor_sync(0xffffffffu, s, o);
    float mu = s * (1.0f/64.0f);
    float dx = v.x - mu, dy = v.y - mu;
    float ss = dx*dx + dy*dy;
    #pragma unroll
    for (int o = 16; o; o >>= 1) ss += __shfl_xor_sync(0xffffffffu, ss, o);
    float rstd = rsqrtf(ss * (1.0f/64.0f) + LN_EPS);
    float2 gg = ((const float2*)g)[lane];
    float2 bb = ((const float2*)b)[lane];
    float2 ov;
    ov.x = dx * rstd * gg.x + bb.x;
    ov.y = dy * rstd * gg.y + bb.y;
    ((float2*)(out + (size_t)tok * D_MODEL))[lane] = ov;
}

// ---------------- launch ----------------
extern "C" void kernel_launch(void* const* d_in, const int* in_sizes, int n_in,
                              void* d_out, int out_size)
{
    const float* cells = (const float*)d_in[0];
    cudaFuncSetAttribute(step_kernel,
                         cudaFuncAttributeMaxDynamicSharedMemorySize, SMEM_BYTES);

    control_kernel<<<1, 128>>>((const float*)d_in[1],
        (const float*)d_in[6],  (const float*)d_in[7],
        (const float*)d_in[8],  (const float*)d_in[9],
        (const float*)d_in[10], (const float*)d_in[11],
        (const float*)d_in[12], (const float*)d_in[13],
        (const float*)d_in[14], (const float*)d_in[15],
        (const float*)d_in[16], (const float*)d_in[17]);

    pack_weights<<<(NRULES*3*16*128 + NRULES*32*64 + 255)/256, 256>>>(
        (const float*)d_in[2], (const float*)d_in[4]);

    for (int j = 0; j < 8; j++)
        step_kernel<<<NBLK, NTHR, SMEM_BYTES>>>(cells,
            (const float*)d_in[3], (const float*)d_in[5], j);

    ln_kernel<<<NTOK/8, 256>>>((const float*)d_in[18], (const float*)d_in[19],
                               (float*)d_out);
}